// round 1
// baseline (speedup 1.0000x reference)
#include <cuda_runtime.h>
#include <cuda_bf16.h>

#define BATCH 4
#define NP    8192
#define NQ    2048
#define CF    64
#define CT    64
#define KS    32
#define R2    0.04f
#define OUTC  (3 + CF)   // 67 channels in grouped_features

// Static scratch: point-major transposed features / t_embed (8MB each).
__device__ float g_feat_t[BATCH * NP * CF];
__device__ float g_temb_t[BATCH * NP * CT];

// [B,C,Np] -> [B,Np,C] tiled transpose (handles both features and t_embed via blockIdx.z).
__global__ void qg_transpose_kernel(const float* __restrict__ feats,
                                    const float* __restrict__ temb) {
    __shared__ float tile[32][33];
    int b     = blockIdx.z >> 1;
    int which = blockIdx.z & 1;
    const float* src = which ? temb : feats;
    float*       dst = which ? g_temb_t : g_feat_t;
    int p0 = blockIdx.x * 32;
    int c0 = blockIdx.y * 32;
    int tx = threadIdx.x, ty = threadIdx.y;
    tile[ty][tx] = src[((size_t)b * CF + (c0 + ty)) * NP + (p0 + tx)];
    __syncthreads();
    dst[((size_t)b * NP + (p0 + ty)) * CF + (c0 + tx)] = tile[tx][ty];
}

// One warp per query: chunked-ballot ball query (first-K in index order, early exit),
// then coalesced gather through a padded smem tile.
__global__ __launch_bounds__(128) void qg_main_kernel(
    const float* __restrict__ coords,
    const float* __restrict__ queries,
    float* __restrict__ out)
{
    __shared__ float tiles[4][KS][65];   // padded: conflict-free column reads
    __shared__ int   slots_s[4][KS];

    int lane = threadIdx.x & 31;
    int w    = threadIdx.x >> 5;
    int g    = blockIdx.x * 4 + w;       // global query id
    int b    = g / NQ;
    int q    = g % NQ;

    const float* qp = queries + ((size_t)b * NQ + q) * 3;
    float qx = qp[0], qy = qp[1], qz = qp[2];

    const float* cb = coords + (size_t)b * NP * 3;
    int* slots = slots_s[w];
    int count = 0;

    // ---- ball query: warp scans 32 points per iteration, appends in index order ----
    for (int base = 0; base < NP && count < KS; base += 32) {
        int i = base + lane;
        float px = cb[i * 3 + 0];
        float py = cb[i * 3 + 1];
        float pz = cb[i * 3 + 2];
        // Match XLA rounding exactly: no FMA contraction.
        float dx = __fadd_rn(qx, -px);
        float dy = __fadd_rn(qy, -py);
        float dz = __fadd_rn(qz, -pz);
        float d2 = __fadd_rn(__fadd_rn(__fmul_rn(dx, dx), __fmul_rn(dy, dy)),
                             __fmul_rn(dz, dz));
        bool in = d2 < R2;
        unsigned m = __ballot_sync(0xffffffffu, in);
        if (in) {
            int slot = count + __popc(m & ((1u << lane) - 1u));
            if (slot < KS) slots[slot] = i;
        }
        count += __popc(m);
    }
    __syncwarp();

    int first = (count > 0) ? slots[0] : 0;   // pad value (0 if no neighbor)
    int my    = (lane < count) ? slots[lane] : first;

    // ---- coords channels (0..2): centered grouped coords ----
    float px = cb[my * 3 + 0];
    float py = cb[my * 3 + 1];
    float pz = cb[my * 3 + 2];
    const size_t stride = (size_t)NQ * KS;
    size_t ob0 = (size_t)b * OUTC * stride + (size_t)q * KS + lane;
    out[ob0]              = px - qx;
    out[ob0 + stride]     = py - qy;
    out[ob0 + 2 * stride] = pz - qz;

    float (*tile)[65] = tiles[w];

    // ---- features: coalesced 256B row loads -> smem transpose -> coalesced stores ----
    {
        const float* ft = g_feat_t + (size_t)b * NP * CF;
        #pragma unroll
        for (int k = 0; k < KS; ++k) {
            int ik = __shfl_sync(0xffffffffu, my, k);
            float2 v = *(const float2*)(ft + (size_t)ik * CF + 2 * lane);
            tile[k][2 * lane]     = v.x;
            tile[k][2 * lane + 1] = v.y;
        }
        __syncwarp();
        float* ob = out + ob0 + 3 * stride;
        #pragma unroll
        for (int c = 0; c < CF; ++c)
            ob[(size_t)c * stride] = tile[lane][c];
        __syncwarp();
    }

    // ---- t_embed: same pattern, second output region ----
    {
        const float* tt = g_temb_t + (size_t)b * NP * CT;
        #pragma unroll
        for (int k = 0; k < KS; ++k) {
            int ik = __shfl_sync(0xffffffffu, my, k);
            float2 v = *(const float2*)(tt + (size_t)ik * CT + 2 * lane);
            tile[k][2 * lane]     = v.x;
            tile[k][2 * lane + 1] = v.y;
        }
        __syncwarp();
        float* ob = out + (size_t)BATCH * OUTC * stride
                        + (size_t)b * CT * stride + (size_t)q * KS + lane;
        #pragma unroll
        for (int c = 0; c < CT; ++c)
            ob[(size_t)c * stride] = tile[lane][c];
    }
}

extern "C" void kernel_launch(void* const* d_in, const int* in_sizes, int n_in,
                              void* d_out, int out_size) {
    const float* coords  = (const float*)d_in[0];  // [B,Np,3]
    const float* feats   = (const float*)d_in[1];  // [B,C,Np]
    const float* temb    = (const float*)d_in[2];  // [B,Ct,Np]
    const float* queries = (const float*)d_in[3];  // [B,Nq,3]
    float* out = (float*)d_out;

    qg_transpose_kernel<<<dim3(NP / 32, CF / 32, BATCH * 2), dim3(32, 32)>>>(feats, temb);
    qg_main_kernel<<<(BATCH * NQ) / 4, 128>>>(coords, queries, out);
}

// round 3
// speedup vs baseline: 1.0925x; 1.0925x over previous
#include <cuda_runtime.h>
#include <cuda_bf16.h>

#define BATCH 4
#define NP    8192
#define NQ    2048
#define CF    64
#define CT    64
#define KS    32
#define R2    0.04f
#define OUTC  (3 + CF)   // 67 channels in grouped_features

// Static scratch: point-major transposed features / t_embed (8MB each) + packed coords.
__device__ float  g_feat_t[BATCH * NP * CF];
__device__ float  g_temb_t[BATCH * NP * CT];
__device__ float4 g_coords4[BATCH * NP];

// [B,C,Np] -> [B,Np,C] tiled transpose (features and t_embed via blockIdx.z).
__global__ void qg_transpose_kernel(const float* __restrict__ feats,
                                    const float* __restrict__ temb) {
    __shared__ float tile[32][33];
    int b     = blockIdx.z >> 1;
    int which = blockIdx.z & 1;
    const float* src = which ? temb : feats;
    float*       dst = which ? g_temb_t : g_feat_t;
    int p0 = blockIdx.x * 32;
    int c0 = blockIdx.y * 32;
    int tx = threadIdx.x, ty = threadIdx.y;
    tile[ty][tx] = src[((size_t)b * CF + (c0 + ty)) * NP + (p0 + tx)];
    __syncthreads();
    dst[((size_t)b * NP + (p0 + ty)) * CF + (c0 + tx)] = tile[tx][ty];
}

// Pack coords [B,Np,3] -> float4 [B*Np] for single-LDG.128 ball-query loads.
__global__ void qg_pack_coords_kernel(const float* __restrict__ coords) {
    int i = blockIdx.x * blockDim.x + threadIdx.x;   // 0 .. B*Np-1
    const float* c = coords + (size_t)i * 3;
    g_coords4[i] = make_float4(c[0], c[1], c[2], 0.0f);
}

// One warp per query. Ball query: 64 points/iter, prefetch next 64 (hides L2 latency).
// Gather: 32-channel chunks through a small padded smem tile (4.2KB/warp -> high occupancy).
__global__ __launch_bounds__(256) void qg_main_kernel(
    const float* __restrict__ queries,
    float* __restrict__ out)
{
    __shared__ float tiles[8][KS][33];
    __shared__ int   slots_s[8][KS];

    int lane = threadIdx.x & 31;
    int w    = threadIdx.x >> 5;
    int g    = blockIdx.x * 8 + w;       // global query id
    int b    = g >> 11;                  // / NQ
    int q    = g & (NQ - 1);

    const float* qp = queries + ((size_t)b * NQ + q) * 3;
    float qx = qp[0], qy = qp[1], qz = qp[2];

    const float4* c4 = g_coords4 + (size_t)b * NP;
    int* slots = slots_s[w];
    int count = 0;
    unsigned lt = (1u << lane) - 1u;

    // Prime the pipeline with the first 64 points.
    float4 a0 = c4[lane];
    float4 a1 = c4[32 + lane];
    int base = 0;
    for (;;) {
        int nb = base + 64;
        bool more = nb < NP;
        float4 n0, n1;
        if (more) { n0 = c4[nb + lane]; n1 = c4[nb + 32 + lane]; }

        // Match XLA rounding exactly: no FMA contraction.
        float dx0 = __fadd_rn(qx, -a0.x), dy0 = __fadd_rn(qy, -a0.y), dz0 = __fadd_rn(qz, -a0.z);
        float d20 = __fadd_rn(__fadd_rn(__fmul_rn(dx0, dx0), __fmul_rn(dy0, dy0)),
                              __fmul_rn(dz0, dz0));
        float dx1 = __fadd_rn(qx, -a1.x), dy1 = __fadd_rn(qy, -a1.y), dz1 = __fadd_rn(qz, -a1.z);
        float d21 = __fadd_rn(__fadd_rn(__fmul_rn(dx1, dx1), __fmul_rn(dy1, dy1)),
                              __fmul_rn(dz1, dz1));
        bool in0 = d20 < R2;
        bool in1 = d21 < R2;
        unsigned m0 = __ballot_sync(0xffffffffu, in0);
        unsigned m1 = __ballot_sync(0xffffffffu, in1);
        if (in0) {
            int s = count + __popc(m0 & lt);
            if (s < KS) slots[s] = base + lane;
        }
        int c1 = count + __popc(m0);
        if (in1) {
            int s = c1 + __popc(m1 & lt);
            if (s < KS) slots[s] = base + 32 + lane;
        }
        count = c1 + __popc(m1);
        if (count >= KS || !more) break;
        a0 = n0; a1 = n1; base = nb;
    }
    __syncwarp();

    int first = (count > 0) ? slots[0] : 0;          // pad value (0 if no neighbor)
    int my    = (lane < (count < KS ? count : KS)) ? slots[lane] : first;

    // ---- coords channels (0..2): centered grouped coords ----
    float4 p = c4[my];
    const size_t stride = (size_t)NQ * KS;
    size_t ob0 = (size_t)b * OUTC * stride + (size_t)q * KS + lane;
    out[ob0]              = p.x - qx;
    out[ob0 + stride]     = p.y - qy;
    out[ob0 + 2 * stride] = p.z - qz;

    float (*tile)[33] = tiles[w];

    // ---- gather: 4 chunks of 32 channels (feat lo/hi, temb lo/hi) ----
    const float* ft = g_feat_t + (size_t)b * NP * CF;
    const float* tt = g_temb_t + (size_t)b * NP * CT;
    size_t featb = ob0 + 3 * stride;
    size_t tembb = (size_t)BATCH * OUTC * stride + (size_t)b * CT * stride
                 + (size_t)q * KS + lane;

    #pragma unroll
    for (int part = 0; part < 4; ++part) {
        const float* src = (part < 2) ? ft : tt;
        int c0 = (part & 1) * 32;
        size_t ob = ((part < 2) ? featb : tembb) + (size_t)c0 * stride;
        #pragma unroll
        for (int k = 0; k < KS; ++k) {
            int ik = __shfl_sync(0xffffffffu, my, k);
            tile[k][lane] = src[(size_t)ik * 64 + c0 + lane];   // coalesced 128B row chunk
        }
        __syncwarp();
        #pragma unroll
        for (int c = 0; c < 32; ++c)
            out[ob + (size_t)c * stride] = tile[lane][c];        // coalesced 128B store
        __syncwarp();
    }
}

extern "C" void kernel_launch(void* const* d_in, const int* in_sizes, int n_in,
                              void* d_out, int out_size) {
    const float* coords  = (const float*)d_in[0];  // [B,Np,3]
    const float* feats   = (const float*)d_in[1];  // [B,C,Np]
    const float* temb    = (const float*)d_in[2];  // [B,Ct,Np]
    const float* queries = (const float*)d_in[3];  // [B,Nq,3]
    float* out = (float*)d_out;

    qg_pack_coords_kernel<<<(BATCH * NP) / 256, 256>>>(coords);
    qg_transpose_kernel<<<dim3(NP / 32, CF / 32, BATCH * 2), dim3(32, 32)>>>(feats, temb);
    qg_main_kernel<<<(BATCH * NQ) / 8, 256>>>(queries, out);
}

// round 4
// speedup vs baseline: 1.1165x; 1.0220x over previous
#include <cuda_runtime.h>
#include <cuda_bf16.h>

#define BATCH 4
#define NP    8192
#define NQ    2048
#define CF    64
#define CT    64
#define KS    32
#define R2    0.04f
#define OUTC  (3 + CF)   // 67 channels in grouped_features

// Static scratch: point-major transposed features / t_embed (8MB each) + packed coords.
__device__ float  g_feat_t[BATCH * NP * CF];
__device__ float  g_temb_t[BATCH * NP * CT];
__device__ float4 g_coords4[BATCH * NP];

// [B,C,Np] -> [B,Np,C] tiled transpose (features and t_embed via blockIdx.z).
__global__ void qg_transpose_kernel(const float* __restrict__ feats,
                                    const float* __restrict__ temb) {
    __shared__ float tile[32][33];
    int b     = blockIdx.z >> 1;
    int which = blockIdx.z & 1;
    const float* src = which ? temb : feats;
    float*       dst = which ? g_temb_t : g_feat_t;
    int p0 = blockIdx.x * 32;
    int c0 = blockIdx.y * 32;
    int tx = threadIdx.x, ty = threadIdx.y;
    tile[ty][tx] = src[((size_t)b * CF + (c0 + ty)) * NP + (p0 + tx)];
    __syncthreads();
    dst[((size_t)b * NP + (p0 + ty)) * CF + (c0 + tx)] = tile[tx][ty];
}

// Pack coords [B,Np,3] -> float4 [B*Np] for single-LDG.128 ball-query loads.
__global__ void qg_pack_coords_kernel(const float* __restrict__ coords) {
    int i = blockIdx.x * blockDim.x + threadIdx.x;   // 0 .. B*Np-1
    const float* c = coords + (size_t)i * 3;
    g_coords4[i] = make_float4(c[0], c[1], c[2], 0.0f);
}

// One warp per query. Ball query: 64 points/iter, prefetch next 64 (hides L2 latency).
// Gather: 32-channel chunks through a small padded smem tile.
// __launch_bounds__(256,4): cap at 64 regs/thread -> 4 blocks (32 warps) per SM.
__global__ __launch_bounds__(256, 4) void qg_main_kernel(
    const float* __restrict__ queries,
    float* __restrict__ out)
{
    __shared__ float tiles[8][KS][33];
    __shared__ int   slots_s[8][KS];

    int lane = threadIdx.x & 31;
    int w    = threadIdx.x >> 5;
    int g    = blockIdx.x * 8 + w;       // global query id
    int b    = g >> 11;                  // / NQ
    int q    = g & (NQ - 1);

    const float* qp = queries + ((size_t)b * NQ + q) * 3;
    float qx = qp[0], qy = qp[1], qz = qp[2];

    const float4* c4 = g_coords4 + (size_t)b * NP;
    int* slots = slots_s[w];
    int count = 0;
    unsigned lt = (1u << lane) - 1u;

    // Prime the pipeline with the first 64 points.
    float4 a0 = c4[lane];
    float4 a1 = c4[32 + lane];
    int base = 0;
    for (;;) {
        int nb = base + 64;
        bool more = nb < NP;
        float4 n0, n1;
        if (more) { n0 = c4[nb + lane]; n1 = c4[nb + 32 + lane]; }

        // Match XLA rounding exactly: no FMA contraction.
        float dx0 = __fadd_rn(qx, -a0.x), dy0 = __fadd_rn(qy, -a0.y), dz0 = __fadd_rn(qz, -a0.z);
        float d20 = __fadd_rn(__fadd_rn(__fmul_rn(dx0, dx0), __fmul_rn(dy0, dy0)),
                              __fmul_rn(dz0, dz0));
        float dx1 = __fadd_rn(qx, -a1.x), dy1 = __fadd_rn(qy, -a1.y), dz1 = __fadd_rn(qz, -a1.z);
        float d21 = __fadd_rn(__fadd_rn(__fmul_rn(dx1, dx1), __fmul_rn(dy1, dy1)),
                              __fmul_rn(dz1, dz1));
        bool in0 = d20 < R2;
        bool in1 = d21 < R2;
        unsigned m0 = __ballot_sync(0xffffffffu, in0);
        unsigned m1 = __ballot_sync(0xffffffffu, in1);
        if (in0) {
            int s = count + __popc(m0 & lt);
            if (s < KS) slots[s] = base + lane;
        }
        int c1 = count + __popc(m0);
        if (in1) {
            int s = c1 + __popc(m1 & lt);
            if (s < KS) slots[s] = base + 32 + lane;
        }
        count = c1 + __popc(m1);
        if (count >= KS || !more) break;
        a0 = n0; a1 = n1; base = nb;
    }
    __syncwarp();

    int first = (count > 0) ? slots[0] : 0;          // pad value (0 if no neighbor)
    int my    = (lane < (count < KS ? count : KS)) ? slots[lane] : first;

    // ---- coords channels (0..2): centered grouped coords ----
    float4 p = c4[my];
    const size_t stride = (size_t)NQ * KS;
    size_t ob0 = (size_t)b * OUTC * stride + (size_t)q * KS + lane;
    out[ob0]              = p.x - qx;
    out[ob0 + stride]     = p.y - qy;
    out[ob0 + 2 * stride] = p.z - qz;

    float (*tile)[33] = tiles[w];

    // ---- gather: 4 chunks of 32 channels (feat lo/hi, temb lo/hi) ----
    const float* ft = g_feat_t + (size_t)b * NP * CF;
    const float* tt = g_temb_t + (size_t)b * NP * CT;
    size_t featb = ob0 + 3 * stride;
    size_t tembb = (size_t)BATCH * OUTC * stride + (size_t)b * CT * stride
                 + (size_t)q * KS + lane;

    #pragma unroll
    for (int part = 0; part < 4; ++part) {
        const float* src = (part < 2) ? ft : tt;
        int c0 = (part & 1) * 32;
        size_t ob = ((part < 2) ? featb : tembb) + (size_t)c0 * stride;
        #pragma unroll
        for (int k = 0; k < KS; ++k) {
            int ik = __shfl_sync(0xffffffffu, my, k);
            tile[k][lane] = src[(size_t)ik * 64 + c0 + lane];   // coalesced 128B row chunk
        }
        __syncwarp();
        #pragma unroll
        for (int c = 0; c < 32; ++c)
            out[ob + (size_t)c * stride] = tile[lane][c];        // coalesced 128B store
        __syncwarp();
    }
}

extern "C" void kernel_launch(void* const* d_in, const int* in_sizes, int n_in,
                              void* d_out, int out_size) {
    const float* coords  = (const float*)d_in[0];  // [B,Np,3]
    const float* feats   = (const float*)d_in[1];  // [B,C,Np]
    const float* temb    = (const float*)d_in[2];  // [B,Ct,Np]
    const float* queries = (const float*)d_in[3];  // [B,Nq,3]
    float* out = (float*)d_out;

    qg_pack_coords_kernel<<<(BATCH * NP) / 256, 256>>>(coords);
    qg_transpose_kernel<<<dim3(NP / 32, CF / 32, BATCH * 2), dim3(32, 32)>>>(feats, temb);
    qg_main_kernel<<<(BATCH * NQ) / 8, 256>>>(queries, out);
}

// round 5
// speedup vs baseline: 1.7476x; 1.5652x over previous
#include <cuda_runtime.h>
#include <cuda_bf16.h>

#define BATCH 4
#define NP    8192
#define NQ    2048
#define CF    64
#define CT    64
#define KS    32
#define R2    0.04f
#define OUTC  (3 + CF)        // 67 channels in grouped_features
#define TILE_PTS 1024

// Static scratch.
__device__ float  g_feat_t[BATCH * NP * CF];   // [B,Np,C] point-major features
__device__ float  g_temb_t[BATCH * NP * CT];
__device__ float4 g_coords4[BATCH * NP];       // packed coords
__device__ int    g_idx[BATCH * NQ * KS];      // ball-query result (padded)

// z=0..7: [B,C,Np]->[B,Np,C] transpose (features / t_embed). z=8: pack coords to float4.
__global__ void qg_prep_kernel(const float* __restrict__ coords,
                               const float* __restrict__ feats,
                               const float* __restrict__ temb) {
    __shared__ float tile[32][33];
    int tx = threadIdx.x, ty = threadIdx.y;
    if (blockIdx.z < 8) {
        int b     = blockIdx.z >> 1;
        int which = blockIdx.z & 1;
        const float* src = which ? temb : feats;
        float*       dst = which ? g_temb_t : g_feat_t;
        int p0 = blockIdx.x * 32;
        int c0 = blockIdx.y * 32;
        tile[ty][tx] = src[((size_t)b * CF + (c0 + ty)) * NP + (p0 + tx)];
        __syncthreads();
        dst[((size_t)b * NP + (p0 + ty)) * CF + (c0 + tx)] = tile[tx][ty];
    } else {
        int i = (blockIdx.y * gridDim.x + blockIdx.x) * 1024 + ty * 32 + tx;
        if (i < BATCH * NP) {
            const float* c = coords + (size_t)i * 3;
            g_coords4[i] = make_float4(c[0], c[1], c[2], 0.0f);
        }
    }
}

// Ball query: block of 8 warps (8 queries) shares smem coord tiles.
// Each warp scans from smem (29cyc) instead of L2 (~234cyc). Writes idx + coord channels.
__global__ __launch_bounds__(256) void qg_ballquery_kernel(
    const float* __restrict__ queries,
    float* __restrict__ out)
{
    __shared__ float4 pts[TILE_PTS];      // 16KB
    __shared__ int    slots_s[8][KS];

    int lane = threadIdx.x & 31;
    int w    = threadIdx.x >> 5;
    int g    = blockIdx.x * 8 + w;
    int b    = g >> 11;
    int q    = g & (NQ - 1);

    const float* qp = queries + ((size_t)b * NQ + q) * 3;
    float qx = qp[0], qy = qp[1], qz = qp[2];
    const float4* c4 = g_coords4 + (size_t)b * NP;
    int* slots = slots_s[w];
    int count = 0;
    unsigned lt = (1u << lane) - 1u;

    for (int t = 0; t < NP; t += TILE_PTS) {
        // cooperative tile load (coalesced, L2-resident coords)
        #pragma unroll
        for (int j = 0; j < TILE_PTS / 256; ++j)
            pts[threadIdx.x + j * 256] = c4[t + threadIdx.x + j * 256];
        __syncthreads();

        if (count < KS) {
            for (int s = 0; s < TILE_PTS / 32 && count < KS; ++s) {
                int i = s * 32 + lane;
                float4 p = pts[i];
                // Match XLA rounding exactly: no FMA contraction.
                float dx = __fadd_rn(qx, -p.x);
                float dy = __fadd_rn(qy, -p.y);
                float dz = __fadd_rn(qz, -p.z);
                float d2 = __fadd_rn(__fadd_rn(__fmul_rn(dx, dx), __fmul_rn(dy, dy)),
                                     __fmul_rn(dz, dz));
                bool in = d2 < R2;
                unsigned m = __ballot_sync(0xffffffffu, in);
                if (in) {
                    int sl = count + __popc(m & lt);
                    if (sl < KS) slots[sl] = t + i;
                }
                count += __popc(m);
            }
        }
        int alldone = __syncthreads_and(count >= KS);
        if (alldone) break;
        __syncthreads();   // protect pts before next tile load
    }
    __syncwarp();

    int cnt   = count < KS ? count : KS;
    int first = (count > 0) ? slots[0] : 0;
    int my    = (lane < cnt) ? slots[lane] : first;
    g_idx[(size_t)g * KS + lane] = my;

    // coord channels 0..2 (centered)
    float4 p = c4[my];
    const size_t stride = (size_t)NQ * KS;
    size_t ob0 = (size_t)b * OUTC * stride + (size_t)q * KS + lane;
    out[ob0]              = p.x - qx;
    out[ob0 + stride]     = p.y - qy;
    out[ob0 + 2 * stride] = p.z - qz;
}

// Gather: one warp per (query, 32-channel part). Row-gather (coalesced 128B) ->
// smem transpose -> coalesced column stores.
__global__ __launch_bounds__(256) void qg_gather_kernel(float* __restrict__ out)
{
    __shared__ float tiles[8][KS][33];

    int lane = threadIdx.x & 31;
    int w    = threadIdx.x >> 5;
    int gi   = blockIdx.x * 8 + w;       // (query, part) id
    int part = gi & 3;
    int g    = gi >> 2;
    int b    = g >> 11;
    int q    = g & (NQ - 1);

    int my = g_idx[(size_t)g * KS + lane];

    const float* src = ((part < 2) ? g_feat_t : g_temb_t) + (size_t)b * NP * 64;
    int c0 = (part & 1) * 32;
    const size_t stride = (size_t)NQ * KS;
    size_t ob;
    if (part < 2)
        ob = (size_t)b * OUTC * stride + (size_t)(3 + c0) * stride + (size_t)q * KS + lane;
    else
        ob = (size_t)BATCH * OUTC * stride + (size_t)b * CT * stride
           + (size_t)c0 * stride + (size_t)q * KS + lane;

    float (*tile)[33] = tiles[w];
    #pragma unroll
    for (int k = 0; k < KS; ++k) {
        int ik = __shfl_sync(0xffffffffu, my, k);
        tile[k][lane] = src[(size_t)ik * 64 + c0 + lane];   // coalesced 128B row chunk
    }
    __syncwarp();
    #pragma unroll
    for (int c = 0; c < 32; ++c)
        out[ob + (size_t)c * stride] = tile[lane][c];        // coalesced 128B store
}

extern "C" void kernel_launch(void* const* d_in, const int* in_sizes, int n_in,
                              void* d_out, int out_size) {
    const float* coords  = (const float*)d_in[0];  // [B,Np,3]
    const float* feats   = (const float*)d_in[1];  // [B,C,Np]
    const float* temb    = (const float*)d_in[2];  // [B,Ct,Np]
    const float* queries = (const float*)d_in[3];  // [B,Nq,3]
    float* out = (float*)d_out;

    qg_prep_kernel<<<dim3(NP / 32, CF / 32, 9), dim3(32, 32)>>>(coords, feats, temb);
    qg_ballquery_kernel<<<(BATCH * NQ) / 8, 256>>>(queries, out);
    qg_gather_kernel<<<(BATCH * NQ * 4) / 8, 256>>>(out);
}

// round 7
// speedup vs baseline: 2.0705x; 1.1848x over previous
#include <cuda_runtime.h>
#include <cuda_bf16.h>

#define BATCH 4
#define NP    8192
#define NQ    2048
#define CF    64
#define CT    64
#define KS    32
#define R2    0.04f
#define OUTC  (3 + CF)        // 67 channels in grouped_features
#define TILE_PTS 2048

// Static scratch.
__device__ float  g_feat_t[BATCH * NP * CF];   // [B,Np,C] point-major features
__device__ float  g_temb_t[BATCH * NP * CT];
__device__ float4 g_coords4[BATCH * NP];       // packed coords
__device__ int    g_idx[BATCH * NQ * KS];      // ball-query result (padded)

// z=0..7: [B,C,Np]->[B,Np,C] vectorized transpose (4 elem/thread, STG.128 out).
// z=8: pack coords to float4.
__global__ void qg_prep_kernel(const float* __restrict__ coords,
                               const float* __restrict__ feats,
                               const float* __restrict__ temb) {
    __shared__ float tile[32][33];
    int tx = threadIdx.x, ty = threadIdx.y;          // (32, 8)
    if (blockIdx.z < 8) {
        int b     = blockIdx.z >> 1;
        int which = blockIdx.z & 1;
        const float* src = which ? temb : feats;
        float*       dst = which ? g_temb_t : g_feat_t;
        int p0 = blockIdx.x * 32;
        int c0 = blockIdx.y * 32;
        #pragma unroll
        for (int j = 0; j < 4; ++j)                   // coalesced loads along Np
            tile[ty + 8 * j][tx] = src[((size_t)b * CF + (c0 + ty + 8 * j)) * NP + (p0 + tx)];
        __syncthreads();
        // store: thread (tx,ty) -> point row p0+tx, channel quad c0+4*ty
        float4 v = make_float4(tile[4 * ty + 0][tx], tile[4 * ty + 1][tx],
                               tile[4 * ty + 2][tx], tile[4 * ty + 3][tx]);
        *(float4*)(dst + ((size_t)b * NP + (p0 + tx)) * CF + c0 + 4 * ty) = v;
    } else {
        int i = (blockIdx.y * gridDim.x + blockIdx.x) * 256 + ty * 32 + tx;
        if (i < BATCH * NP) {
            const float* c = coords + (size_t)i * 3;
            g_coords4[i] = make_float4(c[0], c[1], c[2], 0.0f);
        }
    }
}

// Ball query: block of 8 warps (8 queries) shares a 2048-point smem tile.
__global__ __launch_bounds__(256) void qg_ballquery_kernel(
    const float* __restrict__ queries,
    float* __restrict__ out)
{
    __shared__ float4 pts[TILE_PTS];      // 32KB
    __shared__ int    slots_s[8][KS];

    int lane = threadIdx.x & 31;
    int w    = threadIdx.x >> 5;
    int g    = blockIdx.x * 8 + w;
    int b    = g >> 11;
    int q    = g & (NQ - 1);

    const float* qp = queries + ((size_t)b * NQ + q) * 3;
    float qx = qp[0], qy = qp[1], qz = qp[2];
    const float4* c4 = g_coords4 + (size_t)b * NP;
    int* slots = slots_s[w];
    int count = 0;
    unsigned lt = (1u << lane) - 1u;

    for (int t = 0; t < NP; t += TILE_PTS) {
        #pragma unroll
        for (int j = 0; j < TILE_PTS / 256; ++j)
            pts[threadIdx.x + j * 256] = c4[t + threadIdx.x + j * 256];
        __syncthreads();

        if (count < KS) {
            for (int s = 0; s < TILE_PTS / 32 && count < KS; ++s) {
                int i = s * 32 + lane;
                float4 p = pts[i];
                // Match XLA rounding exactly: no FMA contraction.
                float dx = __fadd_rn(qx, -p.x);
                float dy = __fadd_rn(qy, -p.y);
                float dz = __fadd_rn(qz, -p.z);
                float d2 = __fadd_rn(__fadd_rn(__fmul_rn(dx, dx), __fmul_rn(dy, dy)),
                                     __fmul_rn(dz, dz));
                bool in = d2 < R2;
                unsigned m = __ballot_sync(0xffffffffu, in);
                if (in) {
                    int sl = count + __popc(m & lt);
                    if (sl < KS) slots[sl] = t + i;
                }
                count += __popc(m);
            }
        }
        int alldone = __syncthreads_and(count >= KS);
        if (alldone) break;
        __syncthreads();   // protect pts before next tile load
    }
    __syncwarp();

    int cnt   = count < KS ? count : KS;
    int first = (count > 0) ? slots[0] : 0;
    int my    = (lane < cnt) ? slots[lane] : first;
    g_idx[(size_t)g * KS + lane] = my;

    // coord channels 0..2 (centered)
    float4 p = c4[my];
    const size_t stride = (size_t)NQ * KS;
    size_t ob0 = (size_t)b * OUTC * stride + (size_t)q * KS + lane;
    out[ob0]              = p.x - qx;
    out[ob0 + stride]     = p.y - qy;
    out[ob0 + 2 * stride] = p.z - qz;
}

// Gather: one warp per (query, 32-channel part).
// LDG.128 row quads -> 4x STS.32 (conflict-free) -> 4x LDS.32 (conflict-free) -> STG.128.
__global__ __launch_bounds__(256) void qg_gather_kernel(float* __restrict__ out)
{
    __shared__ float tiles[8][KS][33];

    int lane = threadIdx.x & 31;
    int w    = threadIdx.x >> 5;
    int gi   = blockIdx.x * 8 + w;       // (query, part) id
    int part = gi & 3;
    int g    = gi >> 2;
    int b    = g >> 11;
    int q    = g & (NQ - 1);

    int my = g_idx[(size_t)g * KS + lane];

    const float* src = ((part < 2) ? g_feat_t : g_temb_t) + (size_t)b * NP * 64;
    int c0 = (part & 1) * 32;
    const size_t stride = (size_t)NQ * KS;
    size_t ob;   // base for channel 0 of this part, at element (q, k=0)
    if (part < 2)
        ob = (size_t)b * OUTC * stride + (size_t)(3 + c0) * stride + (size_t)q * KS;
    else
        ob = (size_t)BATCH * OUTC * stride + (size_t)b * CT * stride
           + (size_t)c0 * stride + (size_t)q * KS;

    float (*tile)[33] = tiles[w];
    int kq = lane >> 3;          // 0..3  (k within iteration group)
    int cq = lane & 7;           // 0..7  (channel quad)
    #pragma unroll
    for (int it = 0; it < 8; ++it) {
        int k  = it * 4 + kq;
        int ik = __shfl_sync(0xffffffffu, my, k);
        float4 v = *(const float4*)(src + (size_t)ik * 64 + c0 + cq * 4);  // LDG.128
        tile[k][cq * 4 + 0] = v.x;                                         // scalar STS,
        tile[k][cq * 4 + 1] = v.y;                                         // conflict-free
        tile[k][cq * 4 + 2] = v.z;
        tile[k][cq * 4 + 3] = v.w;
    }
    __syncwarp();
    int k4 = lane & 7;           // k quad: stores k=4*k4..4*k4+3
    int cb = lane >> 3;          // channel offset within iteration
    #pragma unroll
    for (int it = 0; it < 8; ++it) {
        int c = it * 4 + cb;
        float4 v = make_float4(tile[4 * k4 + 0][c], tile[4 * k4 + 1][c],
                               tile[4 * k4 + 2][c], tile[4 * k4 + 3][c]);
        *(float4*)(out + ob + (size_t)c * stride + 4 * k4) = v;            // STG.128
    }
}

extern "C" void kernel_launch(void* const* d_in, const int* in_sizes, int n_in,
                              void* d_out, int out_size) {
    const float* coords  = (const float*)d_in[0];  // [B,Np,3]
    const float* feats   = (const float*)d_in[1];  // [B,C,Np]
    const float* temb    = (const float*)d_in[2];  // [B,Ct,Np]
    const float* queries = (const float*)d_in[3];  // [B,Nq,3]
    float* out = (float*)d_out;

    qg_prep_kernel<<<dim3(NP / 32, CF / 32, 9), dim3(32, 8)>>>(coords, feats, temb);
    qg_ballquery_kernel<<<(BATCH * NQ) / 8, 256>>>(queries, out);
    qg_gather_kernel<<<(BATCH * NQ * 4) / 8, 256>>>(out);
}

// round 8
// speedup vs baseline: 2.1406x; 1.0338x over previous
#include <cuda_runtime.h>
#include <cuda_bf16.h>

#define BATCH 4
#define NP    8192
#define NQ    2048
#define CF    64
#define CT    64
#define KS    32
#define R2    0.04f
#define OUTC  (3 + CF)        // 67 channels in grouped_features
#define QPB   64              // queries per ball-query block

// Static scratch.
__device__ float  g_feat_t[BATCH * NP * CF];   // [B,Np,C] point-major features
__device__ float  g_temb_t[BATCH * NP * CT];
__device__ float4 g_coords4[BATCH * NP];       // packed coords
__device__ int    g_idx[BATCH * NQ * KS];      // ball-query result (padded)

// z=0..7: [B,C,Np]->[B,Np,C] vectorized transpose (4 elem/thread, STG.128 out).
// z=8: pack coords to float4.
__global__ void qg_prep_kernel(const float* __restrict__ coords,
                               const float* __restrict__ feats,
                               const float* __restrict__ temb) {
    __shared__ float tile[32][33];
    int tx = threadIdx.x, ty = threadIdx.y;          // (32, 8)
    if (blockIdx.z < 8) {
        int b     = blockIdx.z >> 1;
        int which = blockIdx.z & 1;
        const float* src = which ? temb : feats;
        float*       dst = which ? g_temb_t : g_feat_t;
        int p0 = blockIdx.x * 32;
        int c0 = blockIdx.y * 32;
        #pragma unroll
        for (int j = 0; j < 4; ++j)                   // coalesced loads along Np
            tile[ty + 8 * j][tx] = src[((size_t)b * CF + (c0 + ty + 8 * j)) * NP + (p0 + tx)];
        __syncthreads();
        float4 v = make_float4(tile[4 * ty + 0][tx], tile[4 * ty + 1][tx],
                               tile[4 * ty + 2][tx], tile[4 * ty + 3][tx]);
        *(float4*)(dst + ((size_t)b * NP + (p0 + tx)) * CF + c0 + 4 * ty) = v;
    } else {
        int i = (blockIdx.y * gridDim.x + blockIdx.x) * 256 + ty * 32 + tx;
        if (i < BATCH * NP) {
            const float* c = coords + (size_t)i * 3;
            g_coords4[i] = make_float4(c[0], c[1], c[2], 0.0f);
        }
    }
}

// Ball query: whole batch cloud resident in 96KB dynamic smem (SoA). 1024 threads,
// 32 warps; each warp scans 2 queries purely from smem, per-warp early exit.
__global__ __launch_bounds__(1024) void qg_ballquery_kernel(
    const float* __restrict__ queries,
    float* __restrict__ out)
{
    extern __shared__ float sxyz[];                  // sx[NP] | sy[NP] | sz[NP]
    float* sx = sxyz;
    float* sy = sxyz + NP;
    float* sz = sxyz + 2 * NP;
    __shared__ int slots_s[32][KS];

    int tid  = threadIdx.x;
    int lane = tid & 31;
    int w    = tid >> 5;
    int b    = blockIdx.x >> 5;                      // 32 blocks per batch
    int blk  = blockIdx.x & 31;

    // Load whole cloud once (coalesced float4 reads, SoA scalar smem writes).
    const float4* c4 = g_coords4 + (size_t)b * NP;
    #pragma unroll
    for (int j = 0; j < NP / 1024; ++j) {
        int i = tid + j * 1024;
        float4 p = c4[i];
        sx[i] = p.x; sy[i] = p.y; sz[i] = p.z;
    }
    __syncthreads();

    int* slots = slots_s[w];
    unsigned lt = (1u << lane) - 1u;
    const size_t stride = (size_t)NQ * KS;

    #pragma unroll
    for (int j = 0; j < 2; ++j) {
        int q = blk * QPB + w + 32 * j;
        int g = b * NQ + q;
        const float* qp = queries + (size_t)g * 3;
        float qx = qp[0], qy = qp[1], qz = qp[2];

        int count = 0;
        for (int base = 0; base < NP; base += 64) {
            int i0 = base + lane, i1 = base + 32 + lane;
            float x0 = sx[i0], y0 = sy[i0], z0 = sz[i0];
            float x1 = sx[i1], y1 = sy[i1], z1 = sz[i1];
            // Match XLA rounding exactly: no FMA contraction.
            float dx0 = __fadd_rn(qx, -x0), dy0 = __fadd_rn(qy, -y0), dz0 = __fadd_rn(qz, -z0);
            float d20 = __fadd_rn(__fadd_rn(__fmul_rn(dx0, dx0), __fmul_rn(dy0, dy0)),
                                  __fmul_rn(dz0, dz0));
            float dx1 = __fadd_rn(qx, -x1), dy1 = __fadd_rn(qy, -y1), dz1 = __fadd_rn(qz, -z1);
            float d21 = __fadd_rn(__fadd_rn(__fmul_rn(dx1, dx1), __fmul_rn(dy1, dy1)),
                                  __fmul_rn(dz1, dz1));
            bool in0 = d20 < R2;
            bool in1 = d21 < R2;
            unsigned m0 = __ballot_sync(0xffffffffu, in0);
            unsigned m1 = __ballot_sync(0xffffffffu, in1);
            if (in0) {
                int s = count + __popc(m0 & lt);
                if (s < KS) slots[s] = i0;
            }
            int c1 = count + __popc(m0);
            if (in1) {
                int s = c1 + __popc(m1 & lt);
                if (s < KS) slots[s] = i1;
            }
            count = c1 + __popc(m1);
            if (count >= KS) break;
        }
        __syncwarp();

        int cnt   = count < KS ? count : KS;
        int first = (count > 0) ? slots[0] : 0;
        int my    = (lane < cnt) ? slots[lane] : first;
        g_idx[(size_t)g * KS + lane] = my;

        // coord channels 0..2 (centered)
        size_t ob0 = (size_t)b * OUTC * stride + (size_t)q * KS + lane;
        out[ob0]              = sx[my] - qx;
        out[ob0 + stride]     = sy[my] - qy;
        out[ob0 + 2 * stride] = sz[my] - qz;
        __syncwarp();
    }
}

// Gather: one warp per (query, 32-channel part).
// LDG.128 row quads -> scalar STS (conflict-free) -> scalar LDS -> STG.128.
__global__ __launch_bounds__(256) void qg_gather_kernel(float* __restrict__ out)
{
    __shared__ float tiles[8][KS][33];

    int lane = threadIdx.x & 31;
    int w    = threadIdx.x >> 5;
    int gi   = blockIdx.x * 8 + w;       // (query, part) id
    int part = gi & 3;
    int g    = gi >> 2;
    int b    = g >> 11;
    int q    = g & (NQ - 1);

    int my = g_idx[(size_t)g * KS + lane];

    const float* src = ((part < 2) ? g_feat_t : g_temb_t) + (size_t)b * NP * 64;
    int c0 = (part & 1) * 32;
    const size_t stride = (size_t)NQ * KS;
    size_t ob;
    if (part < 2)
        ob = (size_t)b * OUTC * stride + (size_t)(3 + c0) * stride + (size_t)q * KS;
    else
        ob = (size_t)BATCH * OUTC * stride + (size_t)b * CT * stride
           + (size_t)c0 * stride + (size_t)q * KS;

    float (*tile)[33] = tiles[w];
    int kq = lane >> 3;
    int cq = lane & 7;
    #pragma unroll
    for (int it = 0; it < 8; ++it) {
        int k  = it * 4 + kq;
        int ik = __shfl_sync(0xffffffffu, my, k);
        float4 v = *(const float4*)(src + (size_t)ik * 64 + c0 + cq * 4);  // LDG.128
        tile[k][cq * 4 + 0] = v.x;
        tile[k][cq * 4 + 1] = v.y;
        tile[k][cq * 4 + 2] = v.z;
        tile[k][cq * 4 + 3] = v.w;
    }
    __syncwarp();
    int k4 = lane & 7;
    int cb = lane >> 3;
    #pragma unroll
    for (int it = 0; it < 8; ++it) {
        int c = it * 4 + cb;
        float4 v = make_float4(tile[4 * k4 + 0][c], tile[4 * k4 + 1][c],
                               tile[4 * k4 + 2][c], tile[4 * k4 + 3][c]);
        *(float4*)(out + ob + (size_t)c * stride + 4 * k4) = v;            // STG.128
    }
}

extern "C" void kernel_launch(void* const* d_in, const int* in_sizes, int n_in,
                              void* d_out, int out_size) {
    const float* coords  = (const float*)d_in[0];  // [B,Np,3]
    const float* feats   = (const float*)d_in[1];  // [B,C,Np]
    const float* temb    = (const float*)d_in[2];  // [B,Ct,Np]
    const float* queries = (const float*)d_in[3];  // [B,Nq,3]
    float* out = (float*)d_out;

    const int dyn_smem = 3 * NP * (int)sizeof(float);   // 96KB
    cudaFuncSetAttribute(qg_ballquery_kernel,
                         cudaFuncAttributeMaxDynamicSharedMemorySize, dyn_smem);

    qg_prep_kernel<<<dim3(NP / 32, CF / 32, 9), dim3(32, 8)>>>(coords, feats, temb);
    qg_ballquery_kernel<<<BATCH * 32, 1024, dyn_smem>>>(queries, out);
    qg_gather_kernel<<<(BATCH * NQ * 4) / 8, 256>>>(out);
}